// round 4
// baseline (speedup 1.0000x reference)
#include <cuda_runtime.h>
#include <cuda_bf16.h>

#define HW   56
#define TS   59          // padded smem row stride
#define KSEL 30
#define NV   14          // pixels per active thread (224 threads * 14 = 3136)
#define TMAX 256         // candidate-list capacity

__global__ __launch_bounds__(256, 4)
void topk_spatial_kernel(const float* __restrict__ x,
                         const float* __restrict__ wgt,
                         const float* __restrict__ bias,
                         float* __restrict__ out,
                         int C)
{
    __shared__ float    tile[58 * TS];   // rows 0..57 (borders zero), stride TS
    __shared__ unsigned hist[256];
    __shared__ float    wsm[10];
    __shared__ unsigned sh_dsel, sh_krem;
    __shared__ float    xmax_sm[8];
    __shared__ int      tcnt;
    __shared__ double   tval[TMAX];
    __shared__ int      tidxs[TMAX];

    const int tid = threadIdx.x;
    const int bc  = blockIdx.x;
    const int ch  = bc % C;
    const float* gx = x   + (size_t)bc * (HW * HW);
    float*       go = out + (size_t)bc * (HW * HW);

    if (tid < 9)  wsm[tid] = wgt[ch * 9 + tid];
    if (tid == 9) wsm[9]   = bias[ch];
    if (tid == 10) tcnt = 0;

    // ---- zero borders of the 58x58 logical tile ----
    if (tid < 232) {
        int i = tid;
        if      (i < 58)  tile[i] = 0.f;
        else if (i < 116) tile[57 * TS + (i - 58)] = 0.f;
        else if (i < 174) tile[(i - 116) * TS] = 0.f;
        else              tile[(i - 174) * TS + 57] = 0.f;
    }

    // ---- load interior (float4), tracking max|x| for the error bound ----
    float maxv = 0.0f;
    const float4* gx4 = reinterpret_cast<const float4*>(gx);
    for (int i = tid; i < (HW * HW) / 4; i += 256) {
        float4 v = gx4[i];
        maxv = fmaxf(maxv, fmaxf(fmaxf(fabsf(v.x), fabsf(v.y)),
                                 fmaxf(fabsf(v.z), fabsf(v.w))));
        int p  = i * 4;
        int r  = p / HW;
        int cc = p - r * HW;
        float* t = &tile[(r + 1) * TS + cc + 1];
        t[0] = v.x; t[1] = v.y; t[2] = v.z; t[3] = v.w;
    }
    #pragma unroll
    for (int d = 16; d > 0; d >>= 1)
        maxv = fmaxf(maxv, __shfl_xor_sync(0xFFFFFFFFu, maxv, d));
    if ((tid & 31) == 0) xmax_sm[tid >> 5] = maxv;
    __syncthreads();

    const float w0 = wsm[0], w1 = wsm[1], w2 = wsm[2];
    const float w3 = wsm[3], w4 = wsm[4], w5 = wsm[5];
    const float w6 = wsm[6], w7 = wsm[7], w8 = wsm[8];
    const float bv = wsm[9];

    const bool active = (tid < 224);
    const int  row  = tid >> 2;           // 0..55
    const int  c0   = (tid & 3) * NV;     // 0,14,28,42
    const int  lane = tid & 31;

    // ---- depthwise 3x3 conv in fp32; order irrelevant (selection is exact later) ----
    unsigned key[NV];
    if (active) {
        const float* t0 = &tile[row * TS + c0];   // r-1 taps
        const float* t1 = t0 + TS;                // r   taps
        const float* t2 = t1 + TS;                // r+1 taps
        float a0 = t0[0], a1 = t0[1];
        float b0 = t1[0], b1 = t1[1];
        float d0 = t2[0], d1 = t2[1];
        #pragma unroll
        for (int j = 0; j < NV; ++j) {
            float a2 = t0[j + 2], b2 = t1[j + 2], d2 = t2[j + 2];
            float s = bv;
            s = fmaf(w0, a0, s); s = fmaf(w1, a1, s); s = fmaf(w2, a2, s);
            s = fmaf(w3, b0, s); s = fmaf(w4, b1, s); s = fmaf(w5, b2, s);
            s = fmaf(w6, d0, s); s = fmaf(w7, d1, s); s = fmaf(w8, d2, s);
            unsigned u = __float_as_uint(s);
            key[j] = u ^ ((unsigned)(((int)u) >> 31) | 0x80000000u);
            a0 = a1; a1 = a2; b0 = b1; b1 = b2; d0 = d1; d1 = d2;
        }
    } else {
        #pragma unroll
        for (int j = 0; j < NV; ++j) key[j] = 0u;
    }

    // ---- rank-KSEL threshold on fp32 keys via 4x8-bit radix select ----
    unsigned prefix = 0;
    unsigned krem   = KSEL;
    #pragma unroll
    for (int pass = 0; pass < 4; ++pass) {
        const int shift = 24 - 8 * pass;
        hist[tid] = 0;
        __syncthreads();

        if (active) {
            #pragma unroll
            for (int j = 0; j < NV; ++j) {
                unsigned v = key[j];
                bool ok = (((unsigned long long)v) >> (shift + 8)) ==
                          (unsigned long long)prefix;
                unsigned digit = ok ? ((v >> shift) & 255u) : 0xFFFFFFFFu;
                unsigned m = __match_any_sync(0xFFFFFFFFu, digit);
                if (ok && ((__ffs(m) - 1) == lane))
                    atomicAdd(&hist[digit], (unsigned)__popc(m));
            }
        }
        __syncthreads();

        if (tid < 32) {
            unsigned loc[8];
            unsigned run = 0;
            #pragma unroll
            for (int j = 7; j >= 0; --j) { run += hist[lane * 8 + j]; loc[j] = run; }
            unsigned laneTotal = run;
            unsigned incl = laneTotal;
            #pragma unroll
            for (int d = 1; d < 32; d <<= 1) {
                unsigned t = __shfl_down_sync(0xFFFFFFFFu, incl, d);
                if (lane + d < 32) incl += t;
            }
            unsigned hiSum = incl - laneTotal;
            #pragma unroll
            for (int j = 0; j < 8; ++j) {
                unsigned suf  = hiSum + loc[j];                         // count >= bin
                unsigned sufn = (j < 7) ? (hiSum + loc[j + 1]) : hiSum; // count >  bin
                if (suf >= krem && sufn < krem) {
                    sh_dsel = (unsigned)(lane * 8 + j);
                    sh_krem = krem - sufn;
                }
            }
        }
        __syncthreads();
        prefix = (prefix << 8) | sh_dsel;
        krem   = sh_krem;
    }

    // ---- guard band: candidates = { s >= Tf - 2E }, a provable superset of
    //      the exact top-KSEL (E uniform per CTA => s-ordering == (s-E)-ordering) ----
    float xmax = xmax_sm[0];
    #pragma unroll
    for (int i = 1; i < 8; ++i) xmax = fmaxf(xmax, xmax_sm[i]);
    const float wsum = fabsf(w0) + fabsf(w1) + fabsf(w2) + fabsf(w3) + fabsf(w4)
                     + fabsf(w5) + fabsf(w6) + fabsf(w7) + fabsf(w8);
    const float E = (wsum * xmax + fabsf(bv)) * 1.2e-6f;   // ~20 ulp bound, 2x margin

    const unsigned Tkey = prefix;
    unsigned tu = (Tkey & 0x80000000u) ? (Tkey ^ 0x80000000u) : ~Tkey;
    const float Tf = __uint_as_float(tu);
    const float Tc = Tf - 2.0f * E;
    unsigned cu = __float_as_uint(Tc);
    const unsigned TcKey = cu ^ ((unsigned)(((int)cu) >> 31) | 0x80000000u);

    // ---- exact (double) recompute for candidates only (~KSEL per plane) ----
    if (active) {
        const float* t0 = &tile[row * TS + c0];
        #pragma unroll
        for (int j = 0; j < NV; ++j) {
            if (key[j] >= TcKey) {
                double s = (double)bv;
                s = fma((double)w0, (double)t0[j],            s);
                s = fma((double)w1, (double)t0[j + 1],        s);
                s = fma((double)w2, (double)t0[j + 2],        s);
                s = fma((double)w3, (double)t0[TS + j],       s);
                s = fma((double)w4, (double)t0[TS + j + 1],   s);
                s = fma((double)w5, (double)t0[TS + j + 2],   s);
                s = fma((double)w6, (double)t0[2*TS + j],     s);
                s = fma((double)w7, (double)t0[2*TS + j + 1], s);
                s = fma((double)w8, (double)t0[2*TS + j + 2], s);
                int pos = atomicAdd(&tcnt, 1);
                if (pos < TMAX) { tval[pos] = s; tidxs[pos] = row * HW + c0 + j; }
            }
        }
    }
    __syncthreads();
    const int ntie = (tcnt < TMAX) ? tcnt : TMAX;

    // ---- keep exactly the top-KSEL candidates by (double desc, index asc) ----
    if (active) {
        float* t1 = &tile[(row + 1) * TS + c0 + 1];    // center x values (owned)
        #pragma unroll
        for (int j = 0; j < NV; ++j) {
            bool keep = false;
            if (key[j] >= TcKey) {
                int myidx = row * HW + c0 + j;
                double mys = 0.0;
                for (int q = 0; q < ntie; ++q)
                    if (tidxs[q] == myidx) mys = tval[q];
                unsigned rnk = 0;
                for (int q = 0; q < ntie; ++q) {
                    double v = tval[q];
                    if (v > mys || (v == mys && tidxs[q] < myidx)) rnk++;
                }
                keep = (rnk < KSEL);
            }
            if (!keep) t1[j] = 0.0f;   // owner-exclusive region, race-free
        }
    }
    __syncthreads();

    float4* go4 = reinterpret_cast<float4*>(go);
    for (int i = tid; i < (HW * HW) / 4; i += 256) {
        int p  = i * 4;
        int r  = p / HW;
        int cc = p - r * HW;
        const float* t = &tile[(r + 1) * TS + cc + 1];
        float4 v;
        v.x = t[0]; v.y = t[1]; v.z = t[2]; v.w = t[3];
        go4[i] = v;
    }
}

extern "C" void kernel_launch(void* const* d_in, const int* in_sizes, int n_in,
                              void* d_out, int out_size)
{
    const float* x  = (const float*)d_in[0];
    const float* w  = (const float*)d_in[1];
    const float* b  = (const float*)d_in[2];
    float*       o  = (float*)d_out;
    int C    = in_sizes[2];               // 384
    int n_bc = in_sizes[0] / (HW * HW);   // 12288
    topk_spatial_kernel<<<n_bc, 256>>>(x, w, b, o, C);
}

// round 6
// speedup vs baseline: 3.0086x; 3.0086x over previous
#include <cuda_runtime.h>
#include <cuda_bf16.h>

#define HW   56
#define TS   59          // padded smem row stride
#define KSEL 30
#define NV   14          // pixels per active thread (224 threads * 14 = 3136)
#define TMAX 96          // candidate-list capacity (expected ~30)

__global__ __launch_bounds__(256, 4)
void topk_spatial_kernel(const float* __restrict__ x,
                         const float* __restrict__ wgt,
                         const float* __restrict__ bias,
                         float* __restrict__ out,
                         int C)
{
    __shared__ float    tile[58 * TS];   // rows 0..57 (borders zero), stride TS
    __shared__ unsigned hist[256];
    __shared__ float    wsm[10];
    __shared__ unsigned sh_dsel, sh_krem;
    __shared__ float    xmax_sm[8];
    __shared__ int      tcnt;
    __shared__ double   csc[TMAX];       // candidate exact scores
    __shared__ int      cidx[TMAX];      // candidate flat indices

    const int tid = threadIdx.x;
    const int bc  = blockIdx.x;
    const int ch  = bc % C;
    const float* gx = x   + (size_t)bc * (HW * HW);
    float*       go = out + (size_t)bc * (HW * HW);

    if (tid < 9)  wsm[tid] = wgt[ch * 9 + tid];
    if (tid == 9) wsm[9]   = bias[ch];
    if (tid == 10) tcnt = 0;

    // ---- zero borders of the 58x58 logical tile ----
    if (tid < 232) {
        int i = tid;
        if      (i < 58)  tile[i] = 0.f;
        else if (i < 116) tile[57 * TS + (i - 58)] = 0.f;
        else if (i < 174) tile[(i - 116) * TS] = 0.f;
        else              tile[(i - 174) * TS + 57] = 0.f;
    }

    // ---- load interior (float4), tracking max|x| for the error bound ----
    float maxv = 0.0f;
    const float4* gx4 = reinterpret_cast<const float4*>(gx);
    for (int i = tid; i < (HW * HW) / 4; i += 256) {
        float4 v = gx4[i];
        maxv = fmaxf(maxv, fmaxf(fmaxf(fabsf(v.x), fabsf(v.y)),
                                 fmaxf(fabsf(v.z), fabsf(v.w))));
        int p  = i * 4;
        int r  = p / HW;
        int cc = p - r * HW;
        float* t = &tile[(r + 1) * TS + cc + 1];
        t[0] = v.x; t[1] = v.y; t[2] = v.z; t[3] = v.w;
    }
    #pragma unroll
    for (int d = 16; d > 0; d >>= 1)
        maxv = fmaxf(maxv, __shfl_xor_sync(0xFFFFFFFFu, maxv, d));
    if ((tid & 31) == 0) xmax_sm[tid >> 5] = maxv;
    __syncthreads();

    const float w0 = wsm[0], w1 = wsm[1], w2 = wsm[2];
    const float w3 = wsm[3], w4 = wsm[4], w5 = wsm[5];
    const float w6 = wsm[6], w7 = wsm[7], w8 = wsm[8];
    const float bv = wsm[9];

    const bool active = (tid < 224);
    const int  row  = tid >> 2;           // 0..55
    const int  c0   = (tid & 3) * NV;     // 0,14,28,42
    const int  lane = tid & 31;

    // ---- depthwise 3x3 conv in fp32 (ordering irrelevant: selection exact later) ----
    unsigned key[NV];
    if (active) {
        const float* t0 = &tile[row * TS + c0];   // r-1 taps
        const float* t1 = t0 + TS;                // r   taps
        const float* t2 = t1 + TS;                // r+1 taps
        float a0 = t0[0], a1 = t0[1];
        float b0 = t1[0], b1 = t1[1];
        float d0 = t2[0], d1 = t2[1];
        #pragma unroll
        for (int j = 0; j < NV; ++j) {
            float a2 = t0[j + 2], b2 = t1[j + 2], d2 = t2[j + 2];
            float s = bv;
            s = fmaf(w0, a0, s); s = fmaf(w1, a1, s); s = fmaf(w2, a2, s);
            s = fmaf(w3, b0, s); s = fmaf(w4, b1, s); s = fmaf(w5, b2, s);
            s = fmaf(w6, d0, s); s = fmaf(w7, d1, s); s = fmaf(w8, d2, s);
            unsigned u = __float_as_uint(s);
            key[j] = u ^ ((unsigned)(((int)u) >> 31) | 0x80000000u);
            a0 = a1; a1 = a2; b0 = b1; b1 = b2; d0 = d1; d1 = d2;
        }
    } else {
        #pragma unroll
        for (int j = 0; j < NV; ++j) key[j] = 0u;
    }

    // ---- rank-KSEL threshold on fp32 keys via 4x8-bit radix select ----
    unsigned prefix = 0;
    unsigned krem   = KSEL;
    #pragma unroll
    for (int pass = 0; pass < 4; ++pass) {
        const int shift = 24 - 8 * pass;
        hist[tid] = 0;
        __syncthreads();

        if (active) {
            #pragma unroll
            for (int j = 0; j < NV; ++j) {
                unsigned v = key[j];
                bool ok = (((unsigned long long)v) >> (shift + 8)) ==
                          (unsigned long long)prefix;
                unsigned digit = ok ? ((v >> shift) & 255u) : 0xFFFFFFFFu;
                unsigned m = __match_any_sync(0xFFFFFFFFu, digit);
                if (ok && ((__ffs(m) - 1) == lane))
                    atomicAdd(&hist[digit], (unsigned)__popc(m));
            }
        }
        __syncthreads();

        if (tid < 32) {
            unsigned loc[8];
            unsigned run = 0;
            #pragma unroll
            for (int j = 7; j >= 0; --j) { run += hist[lane * 8 + j]; loc[j] = run; }
            unsigned laneTotal = run;
            unsigned incl = laneTotal;
            #pragma unroll
            for (int d = 1; d < 32; d <<= 1) {
                unsigned t = __shfl_down_sync(0xFFFFFFFFu, incl, d);
                if (lane + d < 32) incl += t;
            }
            unsigned hiSum = incl - laneTotal;
            #pragma unroll
            for (int j = 0; j < 8; ++j) {
                unsigned suf  = hiSum + loc[j];                         // count >= bin
                unsigned sufn = (j < 7) ? (hiSum + loc[j + 1]) : hiSum; // count >  bin
                if (suf >= krem && sufn < krem) {
                    sh_dsel = (unsigned)(lane * 8 + j);
                    sh_krem = krem - sufn;
                }
            }
        }
        __syncthreads();
        prefix = (prefix << 8) | sh_dsel;
        krem   = sh_krem;
    }

    // ---- guard band: candidates = { s >= Tf - 2E }, provable superset of the
    //      exact top-KSEL (E uniform per CTA => s-order == (s-E)-order) ----
    float xmax = xmax_sm[0];
    #pragma unroll
    for (int i = 1; i < 8; ++i) xmax = fmaxf(xmax, xmax_sm[i]);
    const float wsum = fabsf(w0) + fabsf(w1) + fabsf(w2) + fabsf(w3) + fabsf(w4)
                     + fabsf(w5) + fabsf(w6) + fabsf(w7) + fabsf(w8);
    const float E = (wsum * xmax + fabsf(bv)) * 1.2e-6f;   // ~20 ulp bound, 2x margin

    const unsigned Tkey = prefix;
    unsigned tu = (Tkey & 0x80000000u) ? (Tkey ^ 0x80000000u) : ~Tkey;
    const float Tf = __uint_as_float(tu);
    const float Tc = Tf - 2.0f * E;
    unsigned cu = __float_as_uint(Tc);
    const unsigned TcKey = cu ^ ((unsigned)(((int)cu) >> 31) | 0x80000000u);

    // ---- Phase A: collect candidate indices (tiny divergent body: atomic+STS) ----
    if (active) {
        #pragma unroll
        for (int j = 0; j < NV; ++j) {
            if (key[j] >= TcKey) {
                int pos = atomicAdd(&tcnt, 1);
                if (pos < TMAX) cidx[pos] = row * HW + c0 + j;
            }
        }
    }
    __syncthreads();
    const int ntie = (tcnt < TMAX) ? tcnt : TMAX;

    // ---- Phase B: one thread per candidate recomputes the EXACT double score ----
    if (tid < ntie) {
        int p = cidx[tid];
        int r = p / HW, cc = p - r * HW;
        const float* t0 = &tile[r * TS + cc];     // top-left tap of this pixel
        double s = (double)bv;
        s = fma((double)w0, (double)t0[0],        s);
        s = fma((double)w1, (double)t0[1],        s);
        s = fma((double)w2, (double)t0[2],        s);
        s = fma((double)w3, (double)t0[TS],       s);
        s = fma((double)w4, (double)t0[TS + 1],   s);
        s = fma((double)w5, (double)t0[TS + 2],   s);
        s = fma((double)w6, (double)t0[2*TS],     s);
        s = fma((double)w7, (double)t0[2*TS + 1], s);
        s = fma((double)w8, (double)t0[2*TS + 2], s);
        csc[tid] = s;
    }
    __syncthreads();

    // ---- Phase C: rank candidates by (double desc, index asc); keep = rank < KSEL.
    //      Also: branch-free mask of everything below the candidate band. ----
    bool ckeep = true;
    int  cpos  = -1;
    if (tid < ntie) {
        double mys = csc[tid];
        cpos = cidx[tid];
        unsigned rnk = 0;
        for (int q = 0; q < ntie; ++q) {
            double v = csc[q];
            rnk += (v > mys) || (v == mys && cidx[q] < cpos);
        }
        ckeep = (rnk < KSEL);
    }

    if (active) {
        float* t1 = &tile[(row + 1) * TS + c0 + 1];    // center x values (owned)
        #pragma unroll
        for (int j = 0; j < NV; ++j) {
            float v = t1[j];
            t1[j] = (key[j] >= TcKey) ? v : 0.0f;      // branch-free select
        }
    }
    __syncthreads();

    // scatter-zero the few non-kept candidates (~ntie-KSEL ~ 0-2 stores)
    if (tid < ntie && !ckeep) {
        int r = cpos / HW, cc = cpos - r * HW;
        tile[(r + 1) * TS + cc + 1] = 0.0f;
    }
    __syncthreads();

    // ---- coalesced store ----
    float4* go4 = reinterpret_cast<float4*>(go);
    for (int i = tid; i < (HW * HW) / 4; i += 256) {
        int p  = i * 4;
        int r  = p / HW;
        int cc = p - r * HW;
        const float* t = &tile[(r + 1) * TS + cc + 1];
        float4 v;
        v.x = t[0]; v.y = t[1]; v.z = t[2]; v.w = t[3];
        go4[i] = v;
    }
}

extern "C" void kernel_launch(void* const* d_in, const int* in_sizes, int n_in,
                              void* d_out, int out_size)
{
    const float* x  = (const float*)d_in[0];
    const float* w  = (const float*)d_in[1];
    const float* b  = (const float*)d_in[2];
    float*       o  = (float*)d_out;
    int C    = in_sizes[2];               // 384
    int n_bc = in_sizes[0] / (HW * HW);   // 12288
    topk_spatial_kernel<<<n_bc, 256>>>(x, w, b, o, C);
}

// round 7
// speedup vs baseline: 4.4866x; 1.4913x over previous
#include <cuda_runtime.h>
#include <cuda_bf16.h>

#define HW   56
#define TS   59          // padded smem row stride
#define KSEL 30
#define NV   14          // pixels per active thread (224 threads * 14 = 3136)
#define TMAX 448         // candidate capacity (proven bound 14*30=420 + band margin)

__global__ __launch_bounds__(256, 4)
void topk_spatial_kernel(const float* __restrict__ x,
                         const float* __restrict__ wgt,
                         const float* __restrict__ bias,
                         float* __restrict__ out,
                         int C)
{
    __shared__ float    tile[58 * TS];   // rows 0..57 (borders zero), stride TS
    __shared__ unsigned hist[2][256];    // double-buffered radix histograms
    __shared__ float    wsm[10];
    __shared__ unsigned sh_dsel, sh_krem;
    __shared__ float    xmax_sm[8];
    __shared__ int      tcnt;
    __shared__ double   csc[TMAX];       // candidate exact scores
    __shared__ int      cidx[TMAX];      // candidate flat indices

    const int tid = threadIdx.x;
    const int bc  = blockIdx.x;
    const int ch  = bc % C;
    const float* gx = x   + (size_t)bc * (HW * HW);
    float*       go = out + (size_t)bc * (HW * HW);

    if (tid < 9)  wsm[tid] = wgt[ch * 9 + tid];
    if (tid == 9) wsm[9]   = bias[ch];
    if (tid == 10) tcnt = 0;
    hist[0][tid] = 0;
    hist[1][tid] = 0;

    // ---- zero borders of the 58x58 logical tile ----
    if (tid < 232) {
        int i = tid;
        if      (i < 58)  tile[i] = 0.f;
        else if (i < 116) tile[57 * TS + (i - 58)] = 0.f;
        else if (i < 174) tile[(i - 116) * TS] = 0.f;
        else              tile[(i - 174) * TS + 57] = 0.f;
    }

    // ---- load interior (float4), tracking max|x| for the error bound ----
    float maxv = 0.0f;
    const float4* gx4 = reinterpret_cast<const float4*>(gx);
    for (int i = tid; i < (HW * HW) / 4; i += 256) {
        float4 v = gx4[i];
        maxv = fmaxf(maxv, fmaxf(fmaxf(fabsf(v.x), fabsf(v.y)),
                                 fmaxf(fabsf(v.z), fabsf(v.w))));
        int p  = i * 4;
        int r  = p / HW;
        int cc = p - r * HW;
        float* t = &tile[(r + 1) * TS + cc + 1];
        t[0] = v.x; t[1] = v.y; t[2] = v.z; t[3] = v.w;
    }
    #pragma unroll
    for (int d = 16; d > 0; d >>= 1)
        maxv = fmaxf(maxv, __shfl_xor_sync(0xFFFFFFFFu, maxv, d));
    if ((tid & 31) == 0) xmax_sm[tid >> 5] = maxv;
    __syncthreads();

    const float w0 = wsm[0], w1 = wsm[1], w2 = wsm[2];
    const float w3 = wsm[3], w4 = wsm[4], w5 = wsm[5];
    const float w6 = wsm[6], w7 = wsm[7], w8 = wsm[8];
    const float bv = wsm[9];

    const bool active = (tid < 224);
    const int  row  = tid >> 2;           // 0..55
    const int  c0   = (tid & 3) * NV;     // 0,14,28,42
    const int  lane = tid & 31;

    // ---- fp32 conv; per-thread MAX key tracked (selection made exact later) ----
    unsigned key[NV];
    unsigned maxkey = 0u;
    if (active) {
        const float* t0 = &tile[row * TS + c0];   // r-1 taps
        const float* t1 = t0 + TS;                // r   taps
        const float* t2 = t1 + TS;                // r+1 taps
        float a0 = t0[0], a1 = t0[1];
        float b0 = t1[0], b1 = t1[1];
        float d0 = t2[0], d1 = t2[1];
        #pragma unroll
        for (int j = 0; j < NV; ++j) {
            float a2 = t0[j + 2], b2 = t1[j + 2], d2 = t2[j + 2];
            float s = bv;
            s = fmaf(w0, a0, s); s = fmaf(w1, a1, s); s = fmaf(w2, a2, s);
            s = fmaf(w3, b0, s); s = fmaf(w4, b1, s); s = fmaf(w5, b2, s);
            s = fmaf(w6, d0, s); s = fmaf(w7, d1, s); s = fmaf(w8, d2, s);
            unsigned u = __float_as_uint(s);
            unsigned k = u ^ ((unsigned)(((int)u) >> 31) | 0x80000000u);
            key[j] = k;
            maxkey = (k > maxkey) ? k : maxkey;
            a0 = a1; a1 = a2; b0 = b1; b1 = b2; d0 = d1; d1 = d2;
        }
    } else {
        #pragma unroll
        for (int j = 0; j < NV; ++j) key[j] = 0u;
    }

    // ---- radix select the rank-KSEL value among the 224 per-thread maxima.
    //      Lemma: >=KSEL elements are >= M30  =>  V30 >= M30  =>
    //      {key >= M30 - 2E} is a superset of the exact top-KSEL. ----
    unsigned prefix = 0;
    unsigned krem   = KSEL;
    #pragma unroll
    for (int pass = 0; pass < 4; ++pass) {
        const int cur   = pass & 1;
        const int shift = 24 - 8 * pass;
        {
            unsigned v  = maxkey;
            bool ok = (((unsigned long long)v) >> (shift + 8)) ==
                      (unsigned long long)prefix;
            unsigned digit = ok ? ((v >> shift) & 255u) : 0xFFFFFFFFu;
            unsigned m = __match_any_sync(0xFFFFFFFFu, digit);
            if (ok && ((__ffs(m) - 1) == lane))
                atomicAdd(&hist[cur][digit], (unsigned)__popc(m));
            hist[cur ^ 1][tid] = 0;    // pre-zero buffer for next pass
        }
        __syncthreads();

        if (tid < 32) {
            unsigned loc[8];
            unsigned run = 0;
            #pragma unroll
            for (int j = 7; j >= 0; --j) { run += hist[cur][lane * 8 + j]; loc[j] = run; }
            unsigned laneTotal = run;
            unsigned incl = laneTotal;
            #pragma unroll
            for (int d = 1; d < 32; d <<= 1) {
                unsigned t = __shfl_down_sync(0xFFFFFFFFu, incl, d);
                if (lane + d < 32) incl += t;
            }
            unsigned hiSum = incl - laneTotal;
            #pragma unroll
            for (int j = 0; j < 8; ++j) {
                unsigned suf  = hiSum + loc[j];                         // count >= bin
                unsigned sufn = (j < 7) ? (hiSum + loc[j + 1]) : hiSum; // count >  bin
                if (suf >= krem && sufn < krem) {
                    sh_dsel = (unsigned)(lane * 8 + j);
                    sh_krem = krem - sufn;
                }
            }
        }
        __syncthreads();
        prefix = (prefix << 8) | sh_dsel;
        krem   = sh_krem;
    }
    const unsigned M30key = prefix;

    // ---- guard band: Tc = M30 - 2E (E = rigorous fp32 conv error bound) ----
    float xmax = xmax_sm[0];
    #pragma unroll
    for (int i = 1; i < 8; ++i) xmax = fmaxf(xmax, xmax_sm[i]);
    const float wsum = fabsf(w0) + fabsf(w1) + fabsf(w2) + fabsf(w3) + fabsf(w4)
                     + fabsf(w5) + fabsf(w6) + fabsf(w7) + fabsf(w8);
    const float E = (wsum * xmax + fabsf(bv)) * 1.2e-6f;   // ~20 ulp bound, 2x margin

    unsigned tu = (M30key & 0x80000000u) ? (M30key ^ 0x80000000u) : ~M30key;
    const float Tc = __uint_as_float(tu) - 2.0f * E;
    unsigned cu = __float_as_uint(Tc);
    const unsigned TcKey = cu ^ ((unsigned)(((int)cu) >> 31) | 0x80000000u);

    // ---- Phase A: collect candidate indices (threads with max < Tc skip whole loop) ----
    if (active && maxkey >= TcKey) {
        #pragma unroll
        for (int j = 0; j < NV; ++j) {
            if (key[j] >= TcKey) {
                int pos = atomicAdd(&tcnt, 1);
                if (pos < TMAX) cidx[pos] = row * HW + c0 + j;
            }
        }
    }
    __syncthreads();
    const int ntie = (tcnt < TMAX) ? tcnt : TMAX;

    // ---- Phase B: one thread per candidate recomputes the EXACT double score ----
    for (int t = tid; t < ntie; t += 256) {
        int p = cidx[t];
        int r = p / HW, cc = p - r * HW;
        const float* t0 = &tile[r * TS + cc];     // top-left tap of this pixel
        double s = (double)bv;
        s = fma((double)w0, (double)t0[0],        s);
        s = fma((double)w1, (double)t0[1],        s);
        s = fma((double)w2, (double)t0[2],        s);
        s = fma((double)w3, (double)t0[TS],       s);
        s = fma((double)w4, (double)t0[TS + 1],   s);
        s = fma((double)w5, (double)t0[TS + 2],   s);
        s = fma((double)w6, (double)t0[2*TS],     s);
        s = fma((double)w7, (double)t0[2*TS + 1], s);
        s = fma((double)w8, (double)t0[2*TS + 2], s);
        csc[t] = s;
    }
    __syncthreads();

    // ---- branch-free provisional mask of everything below the candidate band ----
    if (active) {
        float* t1 = &tile[(row + 1) * TS + c0 + 1];    // center x values (owned)
        #pragma unroll
        for (int j = 0; j < NV; ++j) {
            float v = t1[j];
            t1[j] = (key[j] >= TcKey) ? v : 0.0f;
        }
    }
    __syncthreads();

    // ---- Phase C: rank candidates by (double desc, index asc); zero non-top-KSEL ----
    for (int t = tid; t < ntie; t += 256) {
        double mys = csc[t];
        int   cpos = cidx[t];
        unsigned rnk = 0;
        for (int q = 0; q < ntie; ++q) {
            double v = csc[q];
            rnk += (v > mys) || (v == mys && cidx[q] < cpos);
        }
        if (rnk >= KSEL) {
            int r = cpos / HW, cc = cpos - r * HW;
            tile[(r + 1) * TS + cc + 1] = 0.0f;
        }
    }
    __syncthreads();

    // ---- coalesced store ----
    float4* go4 = reinterpret_cast<float4*>(go);
    for (int i = tid; i < (HW * HW) / 4; i += 256) {
        int p  = i * 4;
        int r  = p / HW;
        int cc = p - r * HW;
        const float* t = &tile[(r + 1) * TS + cc + 1];
        float4 v;
        v.x = t[0]; v.y = t[1]; v.z = t[2]; v.w = t[3];
        go4[i] = v;
    }
}

extern "C" void kernel_launch(void* const* d_in, const int* in_sizes, int n_in,
                              void* d_out, int out_size)
{
    const float* x  = (const float*)d_in[0];
    const float* w  = (const float*)d_in[1];
    const float* b  = (const float*)d_in[2];
    float*       o  = (float*)d_out;
    int C    = in_sizes[2];               // 384
    int n_bc = in_sizes[0] / (HW * HW);   // 12288
    topk_spatial_kernel<<<n_bc, 256>>>(x, w, b, o, C);
}